// round 1
// baseline (speedup 1.0000x reference)
#include <cuda_runtime.h>
#include <cuda_bf16.h>
#include <cstdint>

#define NV 100000
#define NE 20000
#define D  256

// Scratch (device globals — no allocation allowed)
__device__ float g_Xagg[(size_t)NE * D];   // per-edge sum of incident X rows
__device__ float g_Y[(size_t)NE * D];      // edge features after GEMM
__device__ float g_cnt_e[NE];
__device__ float g_cnt_v[NV];

// ---------------------------------------------------------------------------
// Phase 1: v2e scatter. One warp per nnz entry: gather X[v] (256 f32 = 64 f4),
// red.add into g_Xagg[e]. Lane 0 also bumps both count histograms.
// ---------------------------------------------------------------------------
__global__ void scatter_v2e(const float* __restrict__ X,
                            const int* __restrict__ vidx,
                            const int* __restrict__ eidx,
                            int nnz) {
    int w = (blockIdx.x * blockDim.x + threadIdx.x) >> 5;
    int lane = threadIdx.x & 31;
    if (w >= nnz) return;
    int v = __ldg(vidx + w);
    int e = __ldg(eidx + w);
    if (lane == 0) {
        atomicAdd(g_cnt_e + e, 1.0f);
        atomicAdd(g_cnt_v + v, 1.0f);
    }
    const float4* src = (const float4*)(X + (size_t)v * D);
    float4* dst = (float4*)(g_Xagg + (size_t)e * D);
#pragma unroll
    for (int i = 0; i < 2; i++) {
        float4 val = __ldg(src + lane + 32 * i);
        asm volatile("red.global.add.v4.f32 [%0], {%1,%2,%3,%4};"
                     :: "l"(dst + lane + 32 * i),
                        "f"(val.x), "f"(val.y), "f"(val.z), "f"(val.w)
                     : "memory");
    }
}

// ---------------------------------------------------------------------------
// Phase 2: Y = (Xagg / max(cnt_e,1)) @ W + b.  Tiled SGEMM, BM=BN=64, BK=16,
// 256 threads, 4x4 per-thread micro-tile, mean-scale fused into A load.
// ---------------------------------------------------------------------------
__global__ void gemm_mean_bias(const float* __restrict__ W,
                               const float* __restrict__ bias,
                               int M) {
    __shared__ float As[16][64];
    __shared__ float Ws[16][64];
    const int tid = threadIdx.x;
    const int row0 = blockIdx.x * 64;
    const int col0 = blockIdx.y * 64;
    const int ty = tid >> 4;       // 0..15
    const int tx = tid & 15;       // 0..15

    float acc[4][4];
#pragma unroll
    for (int i = 0; i < 4; i++)
#pragma unroll
        for (int j = 0; j < 4; j++) acc[i][j] = 0.0f;

    // A-tile load mapping: thread -> (row ar, k-quad kq)
    const int ar = tid >> 2;            // 0..63
    const int kq = (tid & 3) * 4;       // 0,4,8,12
    const int arow = row0 + ar;
    const bool arow_ok = (arow < M);
    float s = 0.0f;
    if (arow_ok) s = 1.0f / fmaxf(__ldg(g_cnt_e + arow), 1.0f);
    const float* Arow = g_Xagg + (size_t)arow * D;

    // W-tile load mapping
    const int wr = tid >> 4;            // 0..15
    const int wc = (tid & 15) * 4;      // 0..60

    for (int k0 = 0; k0 < D; k0 += 16) {
        float4 a = make_float4(0.f, 0.f, 0.f, 0.f);
        if (arow_ok) a = *(const float4*)(Arow + k0 + kq);
        As[kq + 0][ar] = a.x * s;
        As[kq + 1][ar] = a.y * s;
        As[kq + 2][ar] = a.z * s;
        As[kq + 3][ar] = a.w * s;
        float4 wv4 = *(const float4*)(W + (size_t)(k0 + wr) * D + col0 + wc);
        *(float4*)&Ws[wr][wc] = wv4;
        __syncthreads();
#pragma unroll
        for (int k = 0; k < 16; k++) {
            float4 aq = *(const float4*)&As[k][ty * 4];
            float4 wq = *(const float4*)&Ws[k][tx * 4];
            float av[4] = {aq.x, aq.y, aq.z, aq.w};
            float wv[4] = {wq.x, wq.y, wq.z, wq.w};
#pragma unroll
            for (int i = 0; i < 4; i++)
#pragma unroll
                for (int j = 0; j < 4; j++)
                    acc[i][j] += av[i] * wv[j];
        }
        __syncthreads();
    }

    float4 bq = *(const float4*)(bias + col0 + tx * 4);
#pragma unroll
    for (int i = 0; i < 4; i++) {
        int r = row0 + ty * 4 + i;
        if (r < M) {
            float4 o;
            o.x = acc[i][0] + bq.x;
            o.y = acc[i][1] + bq.y;
            o.z = acc[i][2] + bq.z;
            o.w = acc[i][3] + bq.w;
            *(float4*)(g_Y + (size_t)r * D + col0 + tx * 4) = o;
        }
    }
}

// ---------------------------------------------------------------------------
// Phase 3: e2v scatter. One warp per nnz entry: gather Y[e] (L2-resident),
// red.add into out[v].
// ---------------------------------------------------------------------------
__global__ void scatter_e2v(const int* __restrict__ vidx,
                            const int* __restrict__ eidx,
                            float* __restrict__ out,
                            int nnz) {
    int w = (blockIdx.x * blockDim.x + threadIdx.x) >> 5;
    int lane = threadIdx.x & 31;
    if (w >= nnz) return;
    int v = __ldg(vidx + w);
    int e = __ldg(eidx + w);
    const float4* src = (const float4*)(g_Y + (size_t)e * D);
    float4* dst = (float4*)(out + (size_t)v * D);
#pragma unroll
    for (int i = 0; i < 2; i++) {
        float4 val = __ldg(src + lane + 32 * i);
        asm volatile("red.global.add.v4.f32 [%0], {%1,%2,%3,%4};"
                     :: "l"(dst + lane + 32 * i),
                        "f"(val.x), "f"(val.y), "f"(val.z), "f"(val.w)
                     : "memory");
    }
}

// ---------------------------------------------------------------------------
// Phase 4: out = relu(out / max(cnt_v, 1))
// ---------------------------------------------------------------------------
__global__ void finalize(float4* __restrict__ out, int n4) {
    int i = blockIdx.x * blockDim.x + threadIdx.x;
    if (i >= n4) return;
    int v = i >> 6;   // 64 float4 per row
    float s = 1.0f / fmaxf(__ldg(g_cnt_v + v), 1.0f);
    float4 o = out[i];
    o.x = fmaxf(o.x * s, 0.0f);
    o.y = fmaxf(o.y * s, 0.0f);
    o.z = fmaxf(o.z * s, 0.0f);
    o.w = fmaxf(o.w * s, 0.0f);
    out[i] = o;
}

extern "C" void kernel_launch(void* const* d_in, const int* in_sizes, int n_in,
                              void* d_out, int out_size) {
    const float* X    = (const float*)d_in[0];
    const float* W    = (const float*)d_in[1];
    const float* bias = (const float*)d_in[2];
    const int* vidx   = (const int*)d_in[3];
    const int* eidx   = (const int*)d_in[4];
    const int nnz     = in_sizes[3];
    float* out = (float*)d_out;

    void *pXagg, *pCntE, *pCntV;
    cudaGetSymbolAddress(&pXagg, g_Xagg);
    cudaGetSymbolAddress(&pCntE, g_cnt_e);
    cudaGetSymbolAddress(&pCntV, g_cnt_v);

    cudaMemsetAsync(pXagg, 0, sizeof(float) * (size_t)NE * D);
    cudaMemsetAsync(pCntE, 0, sizeof(float) * (size_t)NE);
    cudaMemsetAsync(pCntV, 0, sizeof(float) * (size_t)NV);
    cudaMemsetAsync(d_out, 0, sizeof(float) * (size_t)out_size);

    // warp-per-nnz scatter kernels
    int sblocks = (nnz * 32 + 255) / 256;
    scatter_v2e<<<sblocks, 256>>>(X, vidx, eidx, nnz);

    dim3 ggrid((NE + 63) / 64, D / 64);
    gemm_mean_bias<<<ggrid, 256>>>(W, bias, NE);

    scatter_e2v<<<sblocks, 256>>>(vidx, eidx, out, nnz);

    int n4 = (NV * D) / 4;
    finalize<<<(n4 + 255) / 256, 256>>>((float4*)out, n4);
}

// round 2
// speedup vs baseline: 1.0286x; 1.0286x over previous
#include <cuda_runtime.h>
#include <cuda_bf16.h>
#include <cstdint>

#define NV 100000
#define NE 20000
#define D  256
#define NNZ_MAX 800000

// ----- device scratch (no allocations allowed) -----
__device__ int   g_eptr[NE + 1];
__device__ int   g_vptr[NV + 1];
__device__ int   g_ecur[NE];          // counts, then fill cursors
__device__ int   g_vcur[NV];
__device__ int   g_ecol[NNZ_MAX];     // vertex ids grouped by edge
__device__ int   g_vcol[NNZ_MAX];     // edge ids grouped by vertex
__device__ float g_A[(size_t)NE * D]; // per-edge mean of incident X rows
__device__ float g_Y[(size_t)NE * D]; // edge features after GEMM

// ---------------------------------------------------------------------------
// CSR build step 1: histogram of edge / vertex degrees
// ---------------------------------------------------------------------------
__global__ void hist(const int* __restrict__ vidx, const int* __restrict__ eidx,
                     int nnz) {
    int i = blockIdx.x * blockDim.x + threadIdx.x;
    if (i >= nnz) return;
    atomicAdd(g_ecur + __ldg(eidx + i), 1);
    atomicAdd(g_vcur + __ldg(vidx + i), 1);
}

// ---------------------------------------------------------------------------
// CSR build step 2: single-block exclusive scan (n <= ~100k).
// Reads counts from cur, writes row_ptr, and resets cur to row starts.
// ---------------------------------------------------------------------------
__global__ void scan_excl(int* __restrict__ cur, int* __restrict__ ptr, int n) {
    __shared__ int partial[1024];
    const int tid = threadIdx.x;
    const int chunk = (n + 1023) / 1024;
    const int start = tid * chunk;
    const int end = min(start + chunk, n);
    int s = 0;
    for (int i = start; i < end; i++) s += cur[i];
    partial[tid] = s;
    __syncthreads();
    // Hillis-Steele inclusive scan over 1024 partials
    for (int off = 1; off < 1024; off <<= 1) {
        int v = (tid >= off) ? partial[tid - off] : 0;
        __syncthreads();
        partial[tid] += v;
        __syncthreads();
    }
    int run = (tid == 0) ? 0 : partial[tid - 1];
    for (int i = start; i < end; i++) {
        int c = cur[i];
        ptr[i] = run;
        cur[i] = run;
        run += c;
    }
    if (tid == 1023) ptr[n] = run;
}

// ---------------------------------------------------------------------------
// CSR build step 3: fill adjacency lists
// ---------------------------------------------------------------------------
__global__ void fill(const int* __restrict__ vidx, const int* __restrict__ eidx,
                     int nnz) {
    int i = blockIdx.x * blockDim.x + threadIdx.x;
    if (i >= nnz) return;
    int v = __ldg(vidx + i);
    int e = __ldg(eidx + i);
    int p = atomicAdd(g_ecur + e, 1);
    g_ecol[p] = v;
    int q = atomicAdd(g_vcur + v, 1);
    g_vcol[q] = e;
}

// ---------------------------------------------------------------------------
// Phase v2e: A[e] = mean of X[v] over incident vertices.
// 64 threads per edge (one float4 per thread), register accumulation.
// ---------------------------------------------------------------------------
__global__ void gather_v2e(const float4* __restrict__ X4) {
    const int e = blockIdx.x * 4 + (threadIdx.x >> 6);
    const int lane = threadIdx.x & 63;
    if (e >= NE) return;
    const int beg = g_eptr[e], end = g_eptr[e + 1];
    float4 acc = make_float4(0.f, 0.f, 0.f, 0.f);
    int j = beg;
    for (; j + 1 < end; j += 2) {
        int v0 = __ldg(g_ecol + j);
        int v1 = __ldg(g_ecol + j + 1);
        float4 a = __ldg(X4 + (size_t)v0 * 64 + lane);
        float4 b = __ldg(X4 + (size_t)v1 * 64 + lane);
        acc.x += a.x + b.x; acc.y += a.y + b.y;
        acc.z += a.z + b.z; acc.w += a.w + b.w;
    }
    if (j < end) {
        int v0 = __ldg(g_ecol + j);
        float4 a = __ldg(X4 + (size_t)v0 * 64 + lane);
        acc.x += a.x; acc.y += a.y; acc.z += a.z; acc.w += a.w;
    }
    float s = 1.0f / fmaxf((float)(end - beg), 1.0f);
    acc.x *= s; acc.y *= s; acc.z *= s; acc.w *= s;
    *(float4*)(g_A + (size_t)e * D + lane * 4) = acc;
}

// ---------------------------------------------------------------------------
// GEMM: Y = A @ W + b.  BM=BN=64, BK=16, 256 threads, 4x4 micro-tile.
// ---------------------------------------------------------------------------
__global__ void gemm_bias(const float* __restrict__ W,
                          const float* __restrict__ bias, int M) {
    __shared__ float As[16][64];
    __shared__ float Ws[16][64];
    const int tid = threadIdx.x;
    const int row0 = blockIdx.x * 64;
    const int col0 = blockIdx.y * 64;
    const int ty = tid >> 4;
    const int tx = tid & 15;

    float acc[4][4] = {};

    const int ar = tid >> 2;
    const int kq = (tid & 3) * 4;
    const int arow = row0 + ar;
    const bool arow_ok = (arow < M);
    const float* Arow = g_A + (size_t)arow * D;

    const int wr = tid >> 4;
    const int wc = (tid & 15) * 4;

    for (int k0 = 0; k0 < D; k0 += 16) {
        float4 a = make_float4(0.f, 0.f, 0.f, 0.f);
        if (arow_ok) a = *(const float4*)(Arow + k0 + kq);
        As[kq + 0][ar] = a.x;
        As[kq + 1][ar] = a.y;
        As[kq + 2][ar] = a.z;
        As[kq + 3][ar] = a.w;
        *(float4*)&Ws[wr][wc] = *(const float4*)(W + (size_t)(k0 + wr) * D + col0 + wc);
        __syncthreads();
#pragma unroll
        for (int k = 0; k < 16; k++) {
            float4 aq = *(const float4*)&As[k][ty * 4];
            float4 wq = *(const float4*)&Ws[k][tx * 4];
            float av[4] = {aq.x, aq.y, aq.z, aq.w};
            float wv[4] = {wq.x, wq.y, wq.z, wq.w};
#pragma unroll
            for (int i = 0; i < 4; i++)
#pragma unroll
                for (int j = 0; j < 4; j++)
                    acc[i][j] += av[i] * wv[j];
        }
        __syncthreads();
    }

    float4 bq = *(const float4*)(bias + col0 + tx * 4);
#pragma unroll
    for (int i = 0; i < 4; i++) {
        int r = row0 + ty * 4 + i;
        if (r < M) {
            float4 o;
            o.x = acc[i][0] + bq.x;
            o.y = acc[i][1] + bq.y;
            o.z = acc[i][2] + bq.z;
            o.w = acc[i][3] + bq.w;
            *(float4*)(g_Y + (size_t)r * D + col0 + tx * 4) = o;
        }
    }
}

// ---------------------------------------------------------------------------
// Phase e2v: out[v] = relu(mean of Y[e] over incident edges).
// 64 threads per vertex. Writes d_out exactly once (no memset, no finalize).
// ---------------------------------------------------------------------------
__global__ void gather_e2v(float* __restrict__ out) {
    const int v = blockIdx.x * 4 + (threadIdx.x >> 6);
    const int lane = threadIdx.x & 63;
    if (v >= NV) return;
    const int beg = g_vptr[v], end = g_vptr[v + 1];
    const float4* Y4 = (const float4*)g_Y;
    float4 acc = make_float4(0.f, 0.f, 0.f, 0.f);
    int j = beg;
    for (; j + 1 < end; j += 2) {
        int e0 = __ldg(g_vcol + j);
        int e1 = __ldg(g_vcol + j + 1);
        float4 a = __ldg(Y4 + (size_t)e0 * 64 + lane);
        float4 b = __ldg(Y4 + (size_t)e1 * 64 + lane);
        acc.x += a.x + b.x; acc.y += a.y + b.y;
        acc.z += a.z + b.z; acc.w += a.w + b.w;
    }
    if (j < end) {
        int e0 = __ldg(g_vcol + j);
        float4 a = __ldg(Y4 + (size_t)e0 * 64 + lane);
        acc.x += a.x; acc.y += a.y; acc.z += a.z; acc.w += a.w;
    }
    float s = 1.0f / fmaxf((float)(end - beg), 1.0f);
    float4 o;
    o.x = fmaxf(acc.x * s, 0.0f);
    o.y = fmaxf(acc.y * s, 0.0f);
    o.z = fmaxf(acc.z * s, 0.0f);
    o.w = fmaxf(acc.w * s, 0.0f);
    *(float4*)(out + (size_t)v * D + lane * 4) = o;
}

extern "C" void kernel_launch(void* const* d_in, const int* in_sizes, int n_in,
                              void* d_out, int out_size) {
    const float* X    = (const float*)d_in[0];
    const float* W    = (const float*)d_in[1];
    const float* bias = (const float*)d_in[2];
    const int* vidx   = (const int*)d_in[3];
    const int* eidx   = (const int*)d_in[4];
    const int nnz     = in_sizes[3];
    float* out = (float*)d_out;

    void *pEcur, *pVcur;
    cudaGetSymbolAddress(&pEcur, g_ecur);
    cudaGetSymbolAddress(&pVcur, g_vcur);
    cudaMemsetAsync(pEcur, 0, sizeof(int) * NE);
    cudaMemsetAsync(pVcur, 0, sizeof(int) * NV);

    void *pEptr, *pVptr;
    cudaGetSymbolAddress(&pEptr, g_eptr);
    cudaGetSymbolAddress(&pVptr, g_vptr);

    int nb = (nnz + 255) / 256;
    hist<<<nb, 256>>>(vidx, eidx, nnz);
    scan_excl<<<1, 1024>>>((int*)pEcur, (int*)pEptr, NE);
    scan_excl<<<1, 1024>>>((int*)pVcur, (int*)pVptr, NV);
    fill<<<nb, 256>>>(vidx, eidx, nnz);

    gather_v2e<<<(NE + 3) / 4, 256>>>((const float4*)X);

    dim3 ggrid((NE + 63) / 64, D / 64);
    gemm_bias<<<ggrid, 256>>>(W, bias, NE);

    gather_e2v<<<(NV + 3) / 4, 256>>>(out);
}